// round 2
// baseline (speedup 1.0000x reference)
#include <cuda_runtime.h>
#include <cuda_bf16.h>

// ---------------- problem constants ----------------
#define MAX_NODES 50000
#define CH 128          // in = out = 128
#define BN_EPS 1e-5f

// ---------------- scratch (device globals; no allocation allowed) ----------------
__device__ float g_deg[MAX_NODES];
__device__ float g_dis[MAX_NODES];
__device__ float g_xw[(size_t)MAX_NODES * CH];
__device__ float g_sum[CH];
__device__ float g_sumsq[CH];
__device__ float g_scale[CH];
__device__ float g_shift[CH];

// ---------------- K0: init deg (self loop) + zero BN accumulators ----------------
__global__ void k_init(int N) {
    int i = blockIdx.x * blockDim.x + threadIdx.x;
    if (i < CH) { g_sum[i] = 0.f; g_sumsq[i] = 0.f; }
    if (i < N) g_deg[i] = 1.0f;   // self loop
}

// ---------------- K1: degree at targets ----------------
__global__ void k_degree(const int* __restrict__ ei, int E) {
    int e = blockIdx.x * blockDim.x + threadIdx.x;
    if (e < E) {
        int c = ei[(size_t)E + e];   // col = target
        atomicAdd(&g_deg[c], 1.0f);
    }
}

// ---------------- K2: dis = rsqrt(deg) ----------------
__global__ void k_dis(int N) {
    int i = blockIdx.x * blockDim.x + threadIdx.x;
    if (i < N) g_dis[i] = rsqrtf(g_deg[i]);
}

// ---------------- K3: xw = x @ W^T  (+ fused self-loop init of out) ----------------
// Block: 256 threads computes a 64(node) x 128(out) tile.
// Thread (rg = tid/32 in [0,8), cg = tid%32) computes 8 rows x 4 cols.
__global__ __launch_bounds__(256) void k_gemm(const float* __restrict__ x,
                                              const float* __restrict__ W,
                                              float* __restrict__ out, int N) {
    __shared__ __align__(16) float xs[16][64];
    __shared__ __align__(16) float ws[16][128];

    const int tid = threadIdx.x;
    const int rowbase = blockIdx.x * 64;
    const int cg = tid & 31;
    const int rg = tid >> 5;

    float acc[8][4];
#pragma unroll
    for (int m = 0; m < 8; m++)
#pragma unroll
        for (int c = 0; c < 4; c++) acc[m][c] = 0.f;

    for (int k0 = 0; k0 < CH; k0 += 16) {
        // load x tile: 64 rows x 16 k, as 256 float4 (one per thread)
        {
            int m = tid >> 2, kq = tid & 3;
            int row = rowbase + m;
            float4 v = make_float4(0.f, 0.f, 0.f, 0.f);
            if (row < N)
                v = *reinterpret_cast<const float4*>(x + (size_t)row * CH + k0 + kq * 4);
            xs[kq * 4 + 0][m] = v.x;
            xs[kq * 4 + 1][m] = v.y;
            xs[kq * 4 + 2][m] = v.z;
            xs[kq * 4 + 3][m] = v.w;
        }
        // load W tile: 128 out x 16 k, as 512 float4 (two per thread)
#pragma unroll
        for (int t = 0; t < 2; t++) {
            int j = tid + t * 256;
            int o = j >> 2, kq = j & 3;
            float4 v = *reinterpret_cast<const float4*>(W + o * CH + k0 + kq * 4);
            ws[kq * 4 + 0][o] = v.x;
            ws[kq * 4 + 1][o] = v.y;
            ws[kq * 4 + 2][o] = v.z;
            ws[kq * 4 + 3][o] = v.w;
        }
        __syncthreads();

#pragma unroll
        for (int kk = 0; kk < 16; kk++) {
            float4 xa = *reinterpret_cast<float4*>(&xs[kk][rg * 8]);
            float4 xb = *reinterpret_cast<float4*>(&xs[kk][rg * 8 + 4]);
            float4 wv = *reinterpret_cast<float4*>(&ws[kk][cg * 4]);
            float xr[8] = {xa.x, xa.y, xa.z, xa.w, xb.x, xb.y, xb.z, xb.w};
            float wr[4] = {wv.x, wv.y, wv.z, wv.w};
#pragma unroll
            for (int m = 0; m < 8; m++)
#pragma unroll
                for (int c = 0; c < 4; c++) acc[m][c] = fmaf(xr[m], wr[c], acc[m][c]);
        }
        __syncthreads();
    }

    // epilogue: store xw; init out with self-loop contribution xw * dis^2 (= xw/deg)
#pragma unroll
    for (int m = 0; m < 8; m++) {
        int row = rowbase + rg * 8 + m;
        if (row < N) {
            float d = g_dis[row];
            float sl = d * d;
            float4 v = make_float4(acc[m][0], acc[m][1], acc[m][2], acc[m][3]);
            *reinterpret_cast<float4*>(g_xw + (size_t)row * CH + cg * 4) = v;
            float4 o = make_float4(v.x * sl, v.y * sl, v.z * sl, v.w * sl);
            *reinterpret_cast<float4*>(out + (size_t)row * CH + cg * 4) = o;
        }
    }
}

// ---------------- K4: edge scatter, 1 warp per edge, vectorized RED ----------------
__global__ __launch_bounds__(256) void k_scatter(const int* __restrict__ ei,
                                                 float* __restrict__ out, int E) {
    int gwarp = (blockIdx.x * blockDim.x + threadIdx.x) >> 5;
    int lane = threadIdx.x & 31;
    if (gwarp >= E) return;

    int r = ei[gwarp];               // source (message from)
    int c = ei[(size_t)E + gwarp];   // target (aggregate at)
    float norm = g_dis[r] * g_dis[c];

    float4 v = *reinterpret_cast<const float4*>(g_xw + (size_t)r * CH + lane * 4);
    v.x *= norm; v.y *= norm; v.z *= norm; v.w *= norm;

    float* dst = out + (size_t)c * CH + lane * 4;
    asm volatile("red.global.add.v4.f32 [%0], {%1, %2, %3, %4};"
                 :: "l"(dst), "f"(v.x), "f"(v.y), "f"(v.z), "f"(v.w)
                 : "memory");
}

// ---------------- K5: per-channel sum / sumsq ----------------
__global__ void k_stats(const float* __restrict__ out, int N) {
    int c = threadIdx.x;                 // 128 threads = 128 channels
    float s = 0.f, sq = 0.f;
    for (int i = blockIdx.x; i < N; i += gridDim.x) {
        float v = out[(size_t)i * CH + c];
        s += v;
        sq = fmaf(v, v, sq);
    }
    atomicAdd(&g_sum[c], s);
    atomicAdd(&g_sumsq[c], sq);
}

// ---------------- K6: finalize BN scale/shift ----------------
__global__ void k_bn_final(const float* __restrict__ gamma,
                           const float* __restrict__ beta, int N) {
    int c = threadIdx.x;
    float invN = 1.0f / (float)N;
    float mean = g_sum[c] * invN;
    float var = g_sumsq[c] * invN - mean * mean;
    float sc = gamma[c] * rsqrtf(var + BN_EPS);
    g_scale[c] = sc;
    g_shift[c] = beta[c] - mean * sc;    // note: GCN bias cancels under BN
}

// ---------------- K7: apply BN + ReLU in place ----------------
__global__ void k_apply(float* __restrict__ out, int total4) {
    int i = blockIdx.x * blockDim.x + threadIdx.x;
    if (i >= total4) return;
    float4 v = reinterpret_cast<float4*>(out)[i];
    int c = (i * 4) & (CH - 1);
    v.x = fmaxf(fmaf(v.x, g_scale[c + 0], g_shift[c + 0]), 0.f);
    v.y = fmaxf(fmaf(v.y, g_scale[c + 1], g_shift[c + 1]), 0.f);
    v.z = fmaxf(fmaf(v.z, g_scale[c + 2], g_shift[c + 2]), 0.f);
    v.w = fmaxf(fmaf(v.w, g_scale[c + 3], g_shift[c + 3]), 0.f);
    reinterpret_cast<float4*>(out)[i] = v;
}

// ---------------- launch ----------------
extern "C" void kernel_launch(void* const* d_in, const int* in_sizes, int n_in,
                              void* d_out, int out_size) {
    const float* x = (const float*)d_in[0];
    const int* ei = (const int*)d_in[1];       // JAX default: int64 request -> int32
    const float* W = (const float*)d_in[2];
    // d_in[3] = bias: cancels exactly under BatchNorm -> unused
    const float* gamma = (const float*)d_in[4];
    const float* beta = (const float*)d_in[5];
    float* out = (float*)d_out;

    int N = in_sizes[0] / CH;
    int E = in_sizes[1] / 2;

    k_init<<<(N + 255) / 256, 256>>>(N);
    k_degree<<<(E + 255) / 256, 256>>>(ei, E);
    k_dis<<<(N + 255) / 256, 256>>>(N);
    k_gemm<<<(N + 63) / 64, 256>>>(x, W, out, N);
    // one warp per edge -> 8 edges per 256-thread block
    k_scatter<<<(E + 7) / 8, 256>>>(ei, out, E);
    k_stats<<<512, CH>>>(out, N);
    k_bn_final<<<1, CH>>>(gamma, beta, N);
    int total4 = N * CH / 4;
    k_apply<<<(total4 + 255) / 256, 256>>>(out, total4);
}

// round 3
// speedup vs baseline: 1.0607x; 1.0607x over previous
#include <cuda_runtime.h>
#include <cuda_bf16.h>

// ---------------- problem constants ----------------
#define MAX_NODES 50000
#define MAX_EDGES 810000
#define CH 128
#define BN_EPS 1e-5f

// ---------------- scratch (device globals) ----------------
__device__ int   g_cnt[MAX_NODES];        // in-degree (no self loop)
__device__ int   g_off[MAX_NODES + 1];    // CSR offsets
__device__ int   g_cur[MAX_NODES];        // fill cursors
__device__ int   g_csrc[MAX_EDGES];       // CSR: source node per incoming edge
__device__ float g_dis[MAX_NODES];        // deg^{-1/2} (deg includes self loop)
__device__ float g_xw[(size_t)MAX_NODES * CH];
__device__ float g_sum[CH];
__device__ float g_sumsq[CH];
__device__ float g_scale[CH];
__device__ float g_shift[CH];

// ---------------- K0: zero counters / BN accumulators ----------------
__global__ void k_init(int N) {
    int i = blockIdx.x * blockDim.x + threadIdx.x;
    if (i < CH) { g_sum[i] = 0.f; g_sumsq[i] = 0.f; }
    if (i < N) g_cnt[i] = 0;
}

// ---------------- K1: in-degree histogram at targets ----------------
__global__ void k_hist(const int* __restrict__ ei, int E) {
    int e = blockIdx.x * blockDim.x + threadIdx.x;
    if (e < E) atomicAdd(&g_cnt[ei[(size_t)E + e]], 1);
}

// ---------------- K2: single-block exclusive scan + dis ----------------
__global__ __launch_bounds__(1024) void k_scan(int N, int E) {
    __shared__ int warp_sums[32];
    __shared__ int s_carry;
    const int lane = threadIdx.x & 31;
    const int wid = threadIdx.x >> 5;
    if (threadIdx.x == 0) s_carry = 0;
    __syncthreads();

    for (int base = 0; base < N; base += 1024) {
        int i = base + threadIdx.x;
        int v = (i < N) ? g_cnt[i] : 0;
        // warp inclusive scan
        int x = v;
#pragma unroll
        for (int d = 1; d < 32; d <<= 1) {
            int t = __shfl_up_sync(0xffffffffu, x, d);
            if (lane >= d) x += t;
        }
        if (lane == 31) warp_sums[wid] = x;
        __syncthreads();
        if (wid == 0) {
            int y = warp_sums[lane];
#pragma unroll
            for (int d = 1; d < 32; d <<= 1) {
                int t = __shfl_up_sync(0xffffffffu, y, d);
                if (lane >= d) y += t;
            }
            warp_sums[lane] = y;
        }
        __syncthreads();
        int incl = x + (wid > 0 ? warp_sums[wid - 1] : 0) + s_carry;
        int excl = incl - v;
        if (i < N) {
            g_off[i] = excl;
            g_cur[i] = excl;
            g_dis[i] = rsqrtf((float)(v + 1));   // +1 self loop
        }
        __syncthreads();
        if (threadIdx.x == 1023) s_carry = incl;
        __syncthreads();
    }
    if (threadIdx.x == 0) g_off[N] = E;
}

// ---------------- K3: CSR fill ----------------
__global__ void k_fill(const int* __restrict__ ei, int E) {
    int e = blockIdx.x * blockDim.x + threadIdx.x;
    if (e < E) {
        int r = ei[e];
        int c = ei[(size_t)E + e];
        int pos = atomicAdd(&g_cur[c], 1);
        g_csrc[pos] = r;
    }
}

// ---------------- K4: xw = x @ W^T ----------------
// 128 threads, tile 64 rows x 128 cols, per-thread 8x8 micro-tile.
__global__ __launch_bounds__(128) void k_gemm(const float* __restrict__ x,
                                              const float* __restrict__ W,
                                              int N) {
    __shared__ __align__(16) float xs[16][64];
    __shared__ __align__(16) float ws[16][128];

    const int tid = threadIdx.x;
    const int rowbase = blockIdx.x * 64;
    const int cg = tid & 15;   // 16 col groups x 8 cols
    const int rg = tid >> 4;   // 8 row groups x 8 rows

    float acc[8][8];
#pragma unroll
    for (int m = 0; m < 8; m++)
#pragma unroll
        for (int c = 0; c < 8; c++) acc[m][c] = 0.f;

    for (int k0 = 0; k0 < CH; k0 += 16) {
        // x tile: 64 rows x 16 k = 256 float4, 2 per thread
#pragma unroll
        for (int t = 0; t < 2; t++) {
            int j = tid + t * 128;
            int m = j >> 2, kq = j & 3;
            int row = rowbase + m;
            float4 v = make_float4(0.f, 0.f, 0.f, 0.f);
            if (row < N)
                v = *reinterpret_cast<const float4*>(x + (size_t)row * CH + k0 + kq * 4);
            xs[kq * 4 + 0][m] = v.x;
            xs[kq * 4 + 1][m] = v.y;
            xs[kq * 4 + 2][m] = v.z;
            xs[kq * 4 + 3][m] = v.w;
        }
        // W tile: 128 out x 16 k = 512 float4, 4 per thread
#pragma unroll
        for (int t = 0; t < 4; t++) {
            int j = tid + t * 128;
            int o = j >> 2, kq = j & 3;
            float4 v = *reinterpret_cast<const float4*>(W + o * CH + k0 + kq * 4);
            ws[kq * 4 + 0][o] = v.x;
            ws[kq * 4 + 1][o] = v.y;
            ws[kq * 4 + 2][o] = v.z;
            ws[kq * 4 + 3][o] = v.w;
        }
        __syncthreads();

#pragma unroll
        for (int kk = 0; kk < 16; kk++) {
            float4 xa = *reinterpret_cast<float4*>(&xs[kk][rg * 8]);
            float4 xb = *reinterpret_cast<float4*>(&xs[kk][rg * 8 + 4]);
            float4 wa = *reinterpret_cast<float4*>(&ws[kk][cg * 8]);
            float4 wb = *reinterpret_cast<float4*>(&ws[kk][cg * 8 + 4]);
            float xr[8] = {xa.x, xa.y, xa.z, xa.w, xb.x, xb.y, xb.z, xb.w};
            float wr[8] = {wa.x, wa.y, wa.z, wa.w, wb.x, wb.y, wb.z, wb.w};
#pragma unroll
            for (int m = 0; m < 8; m++)
#pragma unroll
                for (int c = 0; c < 8; c++) acc[m][c] = fmaf(xr[m], wr[c], acc[m][c]);
        }
        __syncthreads();
    }

#pragma unroll
    for (int m = 0; m < 8; m++) {
        int row = rowbase + rg * 8 + m;
        if (row < N) {
            float4 a = make_float4(acc[m][0], acc[m][1], acc[m][2], acc[m][3]);
            float4 b = make_float4(acc[m][4], acc[m][5], acc[m][6], acc[m][7]);
            *reinterpret_cast<float4*>(g_xw + (size_t)row * CH + cg * 8) = a;
            *reinterpret_cast<float4*>(g_xw + (size_t)row * CH + cg * 8 + 4) = b;
        }
    }
}

// ---------------- K5: per-node gather (1 warp per node) ----------------
__global__ __launch_bounds__(256) void k_gather(float* __restrict__ out, int N) {
    int node = (blockIdx.x * blockDim.x + threadIdx.x) >> 5;
    int lane = threadIdx.x & 31;
    if (node >= N) return;

    int start = g_off[node];
    int end = g_off[node + 1];
    float dc = g_dis[node];

    // self loop: xw[node] * dc^2
    float4 acc = *reinterpret_cast<const float4*>(g_xw + (size_t)node * CH + lane * 4);
    float sl = dc * dc;
    acc.x *= sl; acc.y *= sl; acc.z *= sl; acc.w *= sl;

    for (int base = start; base < end; base += 32) {
        int j = base + lane;
        int s = 0;
        float nr = 0.f;
        if (j < end) {
            s = g_csrc[j];
            nr = g_dis[s] * dc;
        }
        int m = min(32, end - base);
#pragma unroll 4
        for (int k = 0; k < m; k++) {
            int ss = __shfl_sync(0xffffffffu, s, k);
            float nn = __shfl_sync(0xffffffffu, nr, k);
            float4 v = *reinterpret_cast<const float4*>(g_xw + (size_t)ss * CH + lane * 4);
            acc.x = fmaf(nn, v.x, acc.x);
            acc.y = fmaf(nn, v.y, acc.y);
            acc.z = fmaf(nn, v.z, acc.z);
            acc.w = fmaf(nn, v.w, acc.w);
        }
    }
    *reinterpret_cast<float4*>(out + (size_t)node * CH + lane * 4) = acc;
}

// ---------------- K6: per-channel sum / sumsq ----------------
__global__ void k_stats(const float* __restrict__ out, int N) {
    int c = threadIdx.x;
    float s = 0.f, sq = 0.f;
    for (int i = blockIdx.x; i < N; i += gridDim.x) {
        float v = out[(size_t)i * CH + c];
        s += v;
        sq = fmaf(v, v, sq);
    }
    atomicAdd(&g_sum[c], s);
    atomicAdd(&g_sumsq[c], sq);
}

// ---------------- K7: finalize BN scale/shift ----------------
__global__ void k_bn_final(const float* __restrict__ gamma,
                           const float* __restrict__ beta, int N) {
    int c = threadIdx.x;
    float invN = 1.0f / (float)N;
    float mean = g_sum[c] * invN;
    float var = g_sumsq[c] * invN - mean * mean;
    float sc = gamma[c] * rsqrtf(var + BN_EPS);
    g_scale[c] = sc;
    g_shift[c] = beta[c] - mean * sc;   // GCN bias cancels under BN
}

// ---------------- K8: apply BN + ReLU ----------------
__global__ void k_apply(float* __restrict__ out, int total4) {
    int i = blockIdx.x * blockDim.x + threadIdx.x;
    if (i >= total4) return;
    float4 v = reinterpret_cast<float4*>(out)[i];
    int c = (i * 4) & (CH - 1);
    v.x = fmaxf(fmaf(v.x, g_scale[c + 0], g_shift[c + 0]), 0.f);
    v.y = fmaxf(fmaf(v.y, g_scale[c + 1], g_shift[c + 1]), 0.f);
    v.z = fmaxf(fmaf(v.z, g_scale[c + 2], g_shift[c + 2]), 0.f);
    v.w = fmaxf(fmaf(v.w, g_scale[c + 3], g_shift[c + 3]), 0.f);
    reinterpret_cast<float4*>(out)[i] = v;
}

// ---------------- launch ----------------
extern "C" void kernel_launch(void* const* d_in, const int* in_sizes, int n_in,
                              void* d_out, int out_size) {
    const float* x = (const float*)d_in[0];
    const int* ei = (const int*)d_in[1];
    const float* W = (const float*)d_in[2];
    // d_in[3] = bias: cancels under BatchNorm
    const float* gamma = (const float*)d_in[4];
    const float* beta = (const float*)d_in[5];
    float* out = (float*)d_out;

    int N = in_sizes[0] / CH;
    int E = in_sizes[1] / 2;

    k_init<<<(N + 255) / 256, 256>>>(N);
    k_hist<<<(E + 255) / 256, 256>>>(ei, E);
    k_scan<<<1, 1024>>>(N, E);
    k_fill<<<(E + 255) / 256, 256>>>(ei, E);
    k_gemm<<<(N + 63) / 64, 128>>>(x, W, N);
    k_gather<<<(N * 32 + 255) / 256, 256>>>(out, N);
    k_stats<<<512, CH>>>(out, N);
    k_bn_final<<<1, CH>>>(gamma, beta, N);
    int total4 = N * CH / 4;
    k_apply<<<(total4 + 255) / 256, 256>>>(out, total4);
}

// round 4
// speedup vs baseline: 1.2292x; 1.1589x over previous
#include <cuda_runtime.h>
#include <cuda_bf16.h>

// ---------------- problem constants ----------------
#define MAX_NODES 50000
#define MAX_EDGES 810000
#define CH 128
#define BN_EPS 1e-5f

// ---------------- scratch (device globals) ----------------
__device__ int   g_cnt[MAX_NODES];        // in-degree (no self loop)
__device__ int   g_off[MAX_NODES + 1];    // CSR offsets
__device__ int   g_rank[MAX_EDGES];       // rank of edge within its target
__device__ int   g_csrc[MAX_EDGES];       // CSR: source node per incoming edge
__device__ float g_dis[MAX_NODES];        // deg^{-1/2} (deg includes self loop)
__device__ float g_xw[(size_t)MAX_NODES * CH];
__device__ float g_sum[CH];
__device__ float g_sumsq[CH];
__device__ float g_scale[CH];
__device__ float g_shift[CH];

// ---------------- K0: zero counters / BN accumulators ----------------
__global__ void k_zero(int N) {
    int i = blockIdx.x * blockDim.x + threadIdx.x;
    if (i < CH) { g_sum[i] = 0.f; g_sumsq[i] = 0.f; }
    if (i < N) g_cnt[i] = 0;
}

// ---------------- K1: in-degree histogram + per-edge rank ----------------
__global__ void k_hist(const int* __restrict__ ei, int E) {
    int e = blockIdx.x * blockDim.x + threadIdx.x;
    if (e < E) {
        int c = ei[(size_t)E + e];
        g_rank[e] = atomicAdd(&g_cnt[c], 1);
    }
}

// ---------------- K2: single-block exclusive scan + dis ----------------
__global__ __launch_bounds__(1024) void k_scan(int N, int E) {
    __shared__ int warp_sums[32];
    __shared__ int s_carry;
    const int lane = threadIdx.x & 31;
    const int wid = threadIdx.x >> 5;
    if (threadIdx.x == 0) s_carry = 0;
    __syncthreads();

    for (int base = 0; base < N; base += 1024) {
        int i = base + threadIdx.x;
        int v = (i < N) ? g_cnt[i] : 0;
        int x = v;
#pragma unroll
        for (int d = 1; d < 32; d <<= 1) {
            int t = __shfl_up_sync(0xffffffffu, x, d);
            if (lane >= d) x += t;
        }
        if (lane == 31) warp_sums[wid] = x;
        __syncthreads();
        if (wid == 0) {
            int y = warp_sums[lane];
#pragma unroll
            for (int d = 1; d < 32; d <<= 1) {
                int t = __shfl_up_sync(0xffffffffu, y, d);
                if (lane >= d) y += t;
            }
            warp_sums[lane] = y;
        }
        __syncthreads();
        int incl = x + (wid > 0 ? warp_sums[wid - 1] : 0) + s_carry;
        int excl = incl - v;
        if (i < N) {
            g_off[i] = excl;
            g_dis[i] = rsqrtf((float)(v + 1));   // +1 self loop
        }
        __syncthreads();
        if (threadIdx.x == 1023) s_carry = incl;
        __syncthreads();
    }
    if (threadIdx.x == 0) g_off[N] = E;
}

// ---------------- K3: CSR fill (no atomics — rank precomputed) ----------------
__global__ void k_fill(const int* __restrict__ ei, int E) {
    int e = blockIdx.x * blockDim.x + threadIdx.x;
    if (e < E) {
        int r = ei[e];
        int c = ei[(size_t)E + e];
        g_csrc[g_off[c] + g_rank[e]] = r;
    }
}

// ---------------- K4: xw = x @ W^T ----------------
// 128 threads, tile 64 rows x 128 cols, per-thread 8x8 micro-tile.
__global__ __launch_bounds__(128) void k_gemm(const float* __restrict__ x,
                                              const float* __restrict__ W,
                                              int N) {
    __shared__ __align__(16) float xs[16][64];
    __shared__ __align__(16) float ws[16][128];

    const int tid = threadIdx.x;
    const int rowbase = blockIdx.x * 64;
    const int cg = tid & 15;   // 16 col groups x 8 cols
    const int rg = tid >> 4;   // 8 row groups x 8 rows

    float acc[8][8];
#pragma unroll
    for (int m = 0; m < 8; m++)
#pragma unroll
        for (int c = 0; c < 8; c++) acc[m][c] = 0.f;

    for (int k0 = 0; k0 < CH; k0 += 16) {
#pragma unroll
        for (int t = 0; t < 2; t++) {
            int j = tid + t * 128;
            int m = j >> 2, kq = j & 3;
            int row = rowbase + m;
            float4 v = make_float4(0.f, 0.f, 0.f, 0.f);
            if (row < N)
                v = *reinterpret_cast<const float4*>(x + (size_t)row * CH + k0 + kq * 4);
            xs[kq * 4 + 0][m] = v.x;
            xs[kq * 4 + 1][m] = v.y;
            xs[kq * 4 + 2][m] = v.z;
            xs[kq * 4 + 3][m] = v.w;
        }
#pragma unroll
        for (int t = 0; t < 4; t++) {
            int j = tid + t * 128;
            int o = j >> 2, kq = j & 3;
            float4 v = *reinterpret_cast<const float4*>(W + o * CH + k0 + kq * 4);
            ws[kq * 4 + 0][o] = v.x;
            ws[kq * 4 + 1][o] = v.y;
            ws[kq * 4 + 2][o] = v.z;
            ws[kq * 4 + 3][o] = v.w;
        }
        __syncthreads();

#pragma unroll
        for (int kk = 0; kk < 16; kk++) {
            float4 xa = *reinterpret_cast<float4*>(&xs[kk][rg * 8]);
            float4 xb = *reinterpret_cast<float4*>(&xs[kk][rg * 8 + 4]);
            float4 wa = *reinterpret_cast<float4*>(&ws[kk][cg * 8]);
            float4 wb = *reinterpret_cast<float4*>(&ws[kk][cg * 8 + 4]);
            float xr[8] = {xa.x, xa.y, xa.z, xa.w, xb.x, xb.y, xb.z, xb.w};
            float wr[8] = {wa.x, wa.y, wa.z, wa.w, wb.x, wb.y, wb.z, wb.w};
#pragma unroll
            for (int m = 0; m < 8; m++)
#pragma unroll
                for (int c = 0; c < 8; c++) acc[m][c] = fmaf(xr[m], wr[c], acc[m][c]);
        }
        __syncthreads();
    }

#pragma unroll
    for (int m = 0; m < 8; m++) {
        int row = rowbase + rg * 8 + m;
        if (row < N) {
            float4 a = make_float4(acc[m][0], acc[m][1], acc[m][2], acc[m][3]);
            float4 b = make_float4(acc[m][4], acc[m][5], acc[m][6], acc[m][7]);
            *reinterpret_cast<float4*>(g_xw + (size_t)row * CH + cg * 8) = a;
            *reinterpret_cast<float4*>(g_xw + (size_t)row * CH + cg * 8 + 4) = b;
        }
    }
}

// ---------------- K5: per-node gather (1 warp per node) ----------------
__global__ __launch_bounds__(256) void k_gather(float* __restrict__ out, int N) {
    int node = (blockIdx.x * blockDim.x + threadIdx.x) >> 5;
    int lane = threadIdx.x & 31;
    if (node >= N) return;

    int start = g_off[node];
    int end = g_off[node + 1];
    float dc = g_dis[node];

    // self loop: xw[node] * dc^2
    float4 acc = *reinterpret_cast<const float4*>(g_xw + (size_t)node * CH + lane * 4);
    float sl = dc * dc;
    acc.x *= sl; acc.y *= sl; acc.z *= sl; acc.w *= sl;

    for (int base = start; base < end; base += 32) {
        int j = base + lane;
        int s = 0;
        float nr = 0.f;
        if (j < end) {
            s = g_csrc[j];
            nr = g_dis[s] * dc;
        }
        int m = min(32, end - base);
#pragma unroll 4
        for (int k = 0; k < m; k++) {
            int ss = __shfl_sync(0xffffffffu, s, k);
            float nn = __shfl_sync(0xffffffffu, nr, k);
            float4 v = *reinterpret_cast<const float4*>(g_xw + (size_t)ss * CH + lane * 4);
            acc.x = fmaf(nn, v.x, acc.x);
            acc.y = fmaf(nn, v.y, acc.y);
            acc.z = fmaf(nn, v.z, acc.z);
            acc.w = fmaf(nn, v.w, acc.w);
        }
    }
    *reinterpret_cast<float4*>(out + (size_t)node * CH + lane * 4) = acc;
}

// ---------------- K6: per-channel sum / sumsq ----------------
__global__ void k_stats(const float* __restrict__ out, int N) {
    int c = threadIdx.x;
    float s = 0.f, sq = 0.f;
    for (int i = blockIdx.x; i < N; i += gridDim.x) {
        float v = out[(size_t)i * CH + c];
        s += v;
        sq = fmaf(v, v, sq);
    }
    atomicAdd(&g_sum[c], s);
    atomicAdd(&g_sumsq[c], sq);
}

// ---------------- K7: finalize BN scale/shift ----------------
__global__ void k_bn_final(const float* __restrict__ gamma,
                           const float* __restrict__ beta, int N) {
    int c = threadIdx.x;
    float invN = 1.0f / (float)N;
    float mean = g_sum[c] * invN;
    float var = g_sumsq[c] * invN - mean * mean;
    float sc = gamma[c] * rsqrtf(var + BN_EPS);
    g_scale[c] = sc;
    g_shift[c] = beta[c] - mean * sc;   // GCN bias cancels under BN
}

// ---------------- K8: apply BN + ReLU ----------------
__global__ void k_apply(float* __restrict__ out, int total4) {
    int i = blockIdx.x * blockDim.x + threadIdx.x;
    if (i >= total4) return;
    float4 v = reinterpret_cast<float4*>(out)[i];
    int c = (i * 4) & (CH - 1);
    v.x = fmaxf(fmaf(v.x, g_scale[c + 0], g_shift[c + 0]), 0.f);
    v.y = fmaxf(fmaf(v.y, g_scale[c + 1], g_shift[c + 1]), 0.f);
    v.z = fmaxf(fmaf(v.z, g_scale[c + 2], g_shift[c + 2]), 0.f);
    v.w = fmaxf(fmaf(v.w, g_scale[c + 3], g_shift[c + 3]), 0.f);
    reinterpret_cast<float4*>(out)[i] = v;
}

// ---------------- launch ----------------
extern "C" void kernel_launch(void* const* d_in, const int* in_sizes, int n_in,
                              void* d_out, int out_size) {
    const float* x = (const float*)d_in[0];
    const int* ei = (const int*)d_in[1];
    const float* W = (const float*)d_in[2];
    // d_in[3] = bias: cancels under BatchNorm
    const float* gamma = (const float*)d_in[4];
    const float* beta = (const float*)d_in[5];
    float* out = (float*)d_out;

    int N = in_sizes[0] / CH;
    int E = in_sizes[1] / 2;

    // Side stream + events (created once, on the correctness call — capture is
    // not active then; reused identically on every subsequent call so the
    // enqueued work is deterministic and fully captured via fork/join events).
    static cudaStream_t s2 = nullptr;
    static cudaEvent_t evFork = nullptr, evJoin = nullptr;
    if (s2 == nullptr) {
        cudaStreamCreateWithFlags(&s2, cudaStreamNonBlocking);
        cudaEventCreateWithFlags(&evFork, cudaEventDisableTiming);
        cudaEventCreateWithFlags(&evJoin, cudaEventDisableTiming);
    }

    // fork: CSR build chain on s2, GEMM on main stream
    cudaEventRecord(evFork, 0);
    cudaStreamWaitEvent(s2, evFork, 0);

    k_zero<<<(N + 255) / 256, 256, 0, s2>>>(N);
    k_hist<<<(E + 255) / 256, 256, 0, s2>>>(ei, E);
    k_scan<<<1, 1024, 0, s2>>>(N, E);
    k_fill<<<(E + 255) / 256, 256, 0, s2>>>(ei, E);

    k_gemm<<<(N + 63) / 64, 128>>>(x, W, N);

    // join
    cudaEventRecord(evJoin, s2);
    cudaStreamWaitEvent(0, evJoin, 0);

    k_gather<<<(N * 32 + 255) / 256, 256>>>(out, N);
    k_stats<<<512, CH>>>(out, N);
    k_bn_final<<<1, CH>>>(gamma, beta, N);
    int total4 = N * CH / 4;
    k_apply<<<(total4 + 255) / 256, 256>>>(out, total4);
}

// round 5
// speedup vs baseline: 1.2312x; 1.0016x over previous
#include <cuda_runtime.h>
#include <cuda_bf16.h>

// ---------------- problem constants ----------------
#define MAX_NODES 50000
#define MAX_EDGES 810000
#define CH 128
#define BN_EPS 1e-5f

// ---------------- scratch (device globals) ----------------
__device__ int   g_cnt[MAX_NODES];        // in-degree (no self loop)
__device__ int   g_off[MAX_NODES + 1];    // CSR offsets
__device__ int   g_rank[MAX_EDGES];       // rank of edge within its target
__device__ int   g_csrc[MAX_EDGES];       // CSR: source node per incoming edge
__device__ float g_norm[MAX_EDGES];       // CSR: dis[src]*dis[dst] per incoming edge
__device__ float g_dis[MAX_NODES];        // deg^{-1/2} (deg includes self loop)
__device__ float g_xw[(size_t)MAX_NODES * CH];
__device__ float g_sum[CH];
__device__ float g_sumsq[CH];
__device__ float g_scale[CH];
__device__ float g_shift[CH];

// ---------------- K0: zero counters / BN accumulators ----------------
__global__ void k_zero(int N) {
    int i = blockIdx.x * blockDim.x + threadIdx.x;
    if (i < CH) { g_sum[i] = 0.f; g_sumsq[i] = 0.f; }
    if (i < N) g_cnt[i] = 0;
}

// ---------------- K1: in-degree histogram + per-edge rank ----------------
__global__ void k_hist(const int* __restrict__ ei, int E) {
    int e = blockIdx.x * blockDim.x + threadIdx.x;
    if (e < E) {
        int c = ei[(size_t)E + e];
        g_rank[e] = atomicAdd(&g_cnt[c], 1);
    }
}

// ---------------- K2: single-block exclusive scan + dis ----------------
__global__ __launch_bounds__(1024) void k_scan(int N, int E) {
    __shared__ int warp_sums[32];
    __shared__ int s_carry;
    const int lane = threadIdx.x & 31;
    const int wid = threadIdx.x >> 5;
    if (threadIdx.x == 0) s_carry = 0;
    __syncthreads();

    for (int base = 0; base < N; base += 1024) {
        int i = base + threadIdx.x;
        int v = (i < N) ? g_cnt[i] : 0;
        int x = v;
#pragma unroll
        for (int d = 1; d < 32; d <<= 1) {
            int t = __shfl_up_sync(0xffffffffu, x, d);
            if (lane >= d) x += t;
        }
        if (lane == 31) warp_sums[wid] = x;
        __syncthreads();
        if (wid == 0) {
            int y = warp_sums[lane];
#pragma unroll
            for (int d = 1; d < 32; d <<= 1) {
                int t = __shfl_up_sync(0xffffffffu, y, d);
                if (lane >= d) y += t;
            }
            warp_sums[lane] = y;
        }
        __syncthreads();
        int incl = x + (wid > 0 ? warp_sums[wid - 1] : 0) + s_carry;
        int excl = incl - v;
        if (i < N) {
            g_off[i] = excl;
            g_dis[i] = rsqrtf((float)(v + 1));   // +1 self loop
        }
        __syncthreads();
        if (threadIdx.x == 1023) s_carry = incl;
        __syncthreads();
    }
    if (threadIdx.x == 0) g_off[N] = E;
}

// ---------------- K3: CSR fill (no atomics) + per-edge norm ----------------
__global__ void k_fill(const int* __restrict__ ei, int E) {
    int e = blockIdx.x * blockDim.x + threadIdx.x;
    if (e < E) {
        int r = ei[e];
        int c = ei[(size_t)E + e];
        int pos = g_off[c] + g_rank[e];
        g_csrc[pos] = r;
        g_norm[pos] = g_dis[r] * g_dis[c];
    }
}

// ---------------- K4: xw = x @ W^T ----------------
// 128 threads, tile 64 rows x 128 cols, per-thread 8x8 micro-tile.
__global__ __launch_bounds__(128) void k_gemm(const float* __restrict__ x,
                                              const float* __restrict__ W,
                                              int N) {
    __shared__ __align__(16) float xs[16][64];
    __shared__ __align__(16) float ws[16][128];

    const int tid = threadIdx.x;
    const int rowbase = blockIdx.x * 64;
    const int cg = tid & 15;
    const int rg = tid >> 4;

    float acc[8][8];
#pragma unroll
    for (int m = 0; m < 8; m++)
#pragma unroll
        for (int c = 0; c < 8; c++) acc[m][c] = 0.f;

    for (int k0 = 0; k0 < CH; k0 += 16) {
#pragma unroll
        for (int t = 0; t < 2; t++) {
            int j = tid + t * 128;
            int m = j >> 2, kq = j & 3;
            int row = rowbase + m;
            float4 v = make_float4(0.f, 0.f, 0.f, 0.f);
            if (row < N)
                v = *reinterpret_cast<const float4*>(x + (size_t)row * CH + k0 + kq * 4);
            xs[kq * 4 + 0][m] = v.x;
            xs[kq * 4 + 1][m] = v.y;
            xs[kq * 4 + 2][m] = v.z;
            xs[kq * 4 + 3][m] = v.w;
        }
#pragma unroll
        for (int t = 0; t < 4; t++) {
            int j = tid + t * 128;
            int o = j >> 2, kq = j & 3;
            float4 v = *reinterpret_cast<const float4*>(W + o * CH + k0 + kq * 4);
            ws[kq * 4 + 0][o] = v.x;
            ws[kq * 4 + 1][o] = v.y;
            ws[kq * 4 + 2][o] = v.z;
            ws[kq * 4 + 3][o] = v.w;
        }
        __syncthreads();

#pragma unroll
        for (int kk = 0; kk < 16; kk++) {
            float4 xa = *reinterpret_cast<float4*>(&xs[kk][rg * 8]);
            float4 xb = *reinterpret_cast<float4*>(&xs[kk][rg * 8 + 4]);
            float4 wa = *reinterpret_cast<float4*>(&ws[kk][cg * 8]);
            float4 wb = *reinterpret_cast<float4*>(&ws[kk][cg * 8 + 4]);
            float xr[8] = {xa.x, xa.y, xa.z, xa.w, xb.x, xb.y, xb.z, xb.w};
            float wr[8] = {wa.x, wa.y, wa.z, wa.w, wb.x, wb.y, wb.z, wb.w};
#pragma unroll
            for (int m = 0; m < 8; m++)
#pragma unroll
                for (int c = 0; c < 8; c++) acc[m][c] = fmaf(xr[m], wr[c], acc[m][c]);
        }
        __syncthreads();
    }

#pragma unroll
    for (int m = 0; m < 8; m++) {
        int row = rowbase + rg * 8 + m;
        if (row < N) {
            float4 a = make_float4(acc[m][0], acc[m][1], acc[m][2], acc[m][3]);
            float4 b = make_float4(acc[m][4], acc[m][5], acc[m][6], acc[m][7]);
            *reinterpret_cast<float4*>(g_xw + (size_t)row * CH + cg * 8) = a;
            *reinterpret_cast<float4*>(g_xw + (size_t)row * CH + cg * 8 + 4) = b;
        }
    }
}

// ---------------- K5: per-node gather (1 warp/node) + fused BN stats ----------------
__global__ __launch_bounds__(256) void k_gather(float* __restrict__ out, int N) {
    __shared__ float s_sum[CH];
    __shared__ float s_sq[CH];
    const int t = threadIdx.x;
    if (t < CH) { s_sum[t] = 0.f; s_sq[t] = 0.f; }
    __syncthreads();

    const int node = (blockIdx.x * 256 + t) >> 5;
    const int lane = t & 31;

    if (node < N) {
        int j = g_off[node];
        const int end = g_off[node + 1];
        float dc = g_dis[node];

        // self loop: xw[node] * dc^2
        float4 acc = *reinterpret_cast<const float4*>(g_xw + (size_t)node * CH + lane * 4);
        float sl = dc * dc;
        acc.x *= sl; acc.y *= sl; acc.z *= sl; acc.w *= sl;

        // unrolled-by-4 neighbor loop: broadcast idx/norm loads + float4 row loads
        for (; j + 4 <= end; j += 4) {
            int s0 = g_csrc[j], s1 = g_csrc[j + 1], s2 = g_csrc[j + 2], s3 = g_csrc[j + 3];
            float n0 = g_norm[j], n1 = g_norm[j + 1], n2 = g_norm[j + 2], n3 = g_norm[j + 3];
            float4 v0 = *reinterpret_cast<const float4*>(g_xw + (size_t)s0 * CH + lane * 4);
            float4 v1 = *reinterpret_cast<const float4*>(g_xw + (size_t)s1 * CH + lane * 4);
            float4 v2 = *reinterpret_cast<const float4*>(g_xw + (size_t)s2 * CH + lane * 4);
            float4 v3 = *reinterpret_cast<const float4*>(g_xw + (size_t)s3 * CH + lane * 4);
            acc.x = fmaf(n0, v0.x, acc.x); acc.y = fmaf(n0, v0.y, acc.y);
            acc.z = fmaf(n0, v0.z, acc.z); acc.w = fmaf(n0, v0.w, acc.w);
            acc.x = fmaf(n1, v1.x, acc.x); acc.y = fmaf(n1, v1.y, acc.y);
            acc.z = fmaf(n1, v1.z, acc.z); acc.w = fmaf(n1, v1.w, acc.w);
            acc.x = fmaf(n2, v2.x, acc.x); acc.y = fmaf(n2, v2.y, acc.y);
            acc.z = fmaf(n2, v2.z, acc.z); acc.w = fmaf(n2, v2.w, acc.w);
            acc.x = fmaf(n3, v3.x, acc.x); acc.y = fmaf(n3, v3.y, acc.y);
            acc.z = fmaf(n3, v3.z, acc.z); acc.w = fmaf(n3, v3.w, acc.w);
        }
        for (; j < end; j++) {
            int s = g_csrc[j];
            float nn = g_norm[j];
            float4 v = *reinterpret_cast<const float4*>(g_xw + (size_t)s * CH + lane * 4);
            acc.x = fmaf(nn, v.x, acc.x); acc.y = fmaf(nn, v.y, acc.y);
            acc.z = fmaf(nn, v.z, acc.z); acc.w = fmaf(nn, v.w, acc.w);
        }

        *reinterpret_cast<float4*>(out + (size_t)node * CH + lane * 4) = acc;

        // fused BN stats: accumulate into block-shared, channels lane*4..+3
        int c4 = lane * 4;
        atomicAdd(&s_sum[c4 + 0], acc.x);
        atomicAdd(&s_sum[c4 + 1], acc.y);
        atomicAdd(&s_sum[c4 + 2], acc.z);
        atomicAdd(&s_sum[c4 + 3], acc.w);
        atomicAdd(&s_sq[c4 + 0], acc.x * acc.x);
        atomicAdd(&s_sq[c4 + 1], acc.y * acc.y);
        atomicAdd(&s_sq[c4 + 2], acc.z * acc.z);
        atomicAdd(&s_sq[c4 + 3], acc.w * acc.w);
    }
    __syncthreads();
    if (t < CH) {
        atomicAdd(&g_sum[t], s_sum[t]);
        atomicAdd(&g_sumsq[t], s_sq[t]);
    }
}

// ---------------- K6: finalize BN scale/shift ----------------
__global__ void k_bn_final(const float* __restrict__ gamma,
                           const float* __restrict__ beta, int N) {
    int c = threadIdx.x;
    float invN = 1.0f / (float)N;
    float mean = g_sum[c] * invN;
    float var = g_sumsq[c] * invN - mean * mean;
    float sc = gamma[c] * rsqrtf(var + BN_EPS);
    g_scale[c] = sc;
    g_shift[c] = beta[c] - mean * sc;   // GCN bias cancels under BN
}

// ---------------- K7: apply BN + ReLU ----------------
__global__ void k_apply(float* __restrict__ out, int total4) {
    int i = blockIdx.x * blockDim.x + threadIdx.x;
    if (i >= total4) return;
    float4 v = reinterpret_cast<float4*>(out)[i];
    int c = (i * 4) & (CH - 1);
    v.x = fmaxf(fmaf(v.x, g_scale[c + 0], g_shift[c + 0]), 0.f);
    v.y = fmaxf(fmaf(v.y, g_scale[c + 1], g_shift[c + 1]), 0.f);
    v.z = fmaxf(fmaf(v.z, g_scale[c + 2], g_shift[c + 2]), 0.f);
    v.w = fmaxf(fmaf(v.w, g_scale[c + 3], g_shift[c + 3]), 0.f);
    reinterpret_cast<float4*>(out)[i] = v;
}

// ---------------- launch ----------------
extern "C" void kernel_launch(void* const* d_in, const int* in_sizes, int n_in,
                              void* d_out, int out_size) {
    const float* x = (const float*)d_in[0];
    const int* ei = (const int*)d_in[1];
    const float* W = (const float*)d_in[2];
    // d_in[3] = bias: cancels under BatchNorm
    const float* gamma = (const float*)d_in[4];
    const float* beta = (const float*)d_in[5];
    float* out = (float*)d_out;

    int N = in_sizes[0] / CH;
    int E = in_sizes[1] / 2;

    static cudaStream_t s2 = nullptr;
    static cudaEvent_t evFork = nullptr, evJoin = nullptr;
    if (s2 == nullptr) {
        cudaStreamCreateWithFlags(&s2, cudaStreamNonBlocking);
        cudaEventCreateWithFlags(&evFork, cudaEventDisableTiming);
        cudaEventCreateWithFlags(&evJoin, cudaEventDisableTiming);
    }

    // fork: CSR build chain on s2, GEMM on main stream
    cudaEventRecord(evFork, 0);
    cudaStreamWaitEvent(s2, evFork, 0);

    k_zero<<<(N + 255) / 256, 256, 0, s2>>>(N);
    k_hist<<<(E + 255) / 256, 256, 0, s2>>>(ei, E);
    k_scan<<<1, 1024, 0, s2>>>(N, E);
    k_fill<<<(E + 255) / 256, 256, 0, s2>>>(ei, E);

    k_gemm<<<(N + 63) / 64, 128>>>(x, W, N);

    // join
    cudaEventRecord(evJoin, s2);
    cudaStreamWaitEvent(0, evJoin, 0);

    k_gather<<<(N * 32 + 255) / 256, 256>>>(out, N);
    k_bn_final<<<1, CH>>>(gamma, beta, N);
    int total4 = N * CH / 4;
    k_apply<<<(total4 + 255) / 256, 256>>>(out, total4);
}

// round 6
// speedup vs baseline: 1.3324x; 1.0822x over previous
#include <cuda_runtime.h>
#include <cuda_bf16.h>
#include <mma.h>

using namespace nvcuda;

// ---------------- problem constants ----------------
#define MAX_NODES 50000
#define PAD_NODES 50048         // 782 * 64, GEMM stores unguarded into padding
#define MAX_EDGES 810000
#define CH 128
#define BN_EPS 1e-5f

// ---------------- scratch (device globals) ----------------
__device__ int   g_cnt[MAX_NODES];        // in-degree (no self loop)
__device__ int   g_off[MAX_NODES + 1];    // CSR offsets
__device__ int   g_rank[MAX_EDGES];       // rank of edge within its target
__device__ int   g_csrc[MAX_EDGES];       // CSR: source node per incoming edge
__device__ float g_dis[MAX_NODES];        // deg^{-1/2} (deg includes self loop)
__device__ float g_xw[(size_t)PAD_NODES * CH];
__device__ float g_sum[CH];
__device__ float g_sumsq[CH];
__device__ float g_scale[CH];
__device__ float g_shift[CH];

// ---------------- K1: in-degree histogram + per-edge rank (4 edges/thread) ----------------
__global__ void k_hist(const int* __restrict__ ei, int E) {
    int base = (blockIdx.x * blockDim.x + threadIdx.x) * 4;
    if (base + 4 <= E) {
        int4 c = *reinterpret_cast<const int4*>(ei + (size_t)E + base);
        g_rank[base + 0] = atomicAdd(&g_cnt[c.x], 1);
        g_rank[base + 1] = atomicAdd(&g_cnt[c.y], 1);
        g_rank[base + 2] = atomicAdd(&g_cnt[c.z], 1);
        g_rank[base + 3] = atomicAdd(&g_cnt[c.w], 1);
    } else {
        for (int e = base; e < E; e++)
            g_rank[e] = atomicAdd(&g_cnt[ei[(size_t)E + e]], 1);
    }
}

// ---------------- K2: single-block exclusive scan + dis (+ zero BN accum) ----------------
__global__ __launch_bounds__(1024) void k_scan(int N, int E) {
    __shared__ int warp_sums[32];
    __shared__ int s_carry;
    const int lane = threadIdx.x & 31;
    const int wid = threadIdx.x >> 5;
    if (threadIdx.x < CH) { g_sum[threadIdx.x] = 0.f; g_sumsq[threadIdx.x] = 0.f; }
    if (threadIdx.x == 0) s_carry = 0;
    __syncthreads();

    for (int base = 0; base < N; base += 1024) {
        int i = base + threadIdx.x;
        int v = (i < N) ? g_cnt[i] : 0;
        int x = v;
#pragma unroll
        for (int d = 1; d < 32; d <<= 1) {
            int t = __shfl_up_sync(0xffffffffu, x, d);
            if (lane >= d) x += t;
        }
        if (lane == 31) warp_sums[wid] = x;
        __syncthreads();
        if (wid == 0) {
            int y = warp_sums[lane];
#pragma unroll
            for (int d = 1; d < 32; d <<= 1) {
                int t = __shfl_up_sync(0xffffffffu, y, d);
                if (lane >= d) y += t;
            }
            warp_sums[lane] = y;
        }
        __syncthreads();
        int incl = x + (wid > 0 ? warp_sums[wid - 1] : 0) + s_carry;
        int excl = incl - v;
        if (i < N) {
            g_off[i] = excl;
            g_dis[i] = rsqrtf((float)(v + 1));   // +1 self loop
        }
        __syncthreads();
        if (threadIdx.x == 1023) s_carry = incl;
        __syncthreads();
    }
    if (threadIdx.x == 0) g_off[N] = E;
}

// ---------------- K3: CSR fill, no atomics (4 edges/thread) ----------------
__global__ void k_fill(const int* __restrict__ ei, int E) {
    int base = (blockIdx.x * blockDim.x + threadIdx.x) * 4;
    if (base + 4 <= E) {
        int4 r = *reinterpret_cast<const int4*>(ei + base);
        int4 c = *reinterpret_cast<const int4*>(ei + (size_t)E + base);
        int4 k = *reinterpret_cast<const int4*>(g_rank + base);
        g_csrc[g_off[c.x] + k.x] = r.x;
        g_csrc[g_off[c.y] + k.y] = r.y;
        g_csrc[g_off[c.z] + k.z] = r.z;
        g_csrc[g_off[c.w] + k.w] = r.w;
    } else {
        for (int e = base; e < E; e++)
            g_csrc[g_off[ei[(size_t)E + e]] + g_rank[e]] = ei[e];
    }
}

// ---------------- K4: xw = x @ W^T via bf16-split wmma ----------------
// 256 threads, tile 64(M) x 128(N), warps 2x4, each warp 2x2 m16n16k16 frags.
// x = hi + lo (bf16 each); xw = hi*hi + hi*lo + lo*hi (fp32 accumulate).
__global__ __launch_bounds__(256) void k_gemm(const float* __restrict__ x,
                                              const float* __restrict__ W,
                                              int N) {
    __shared__ __nv_bfloat16 xhi[64 * 16], xlo[64 * 16];
    __shared__ __nv_bfloat16 whi[128 * 16], wlo[128 * 16];

    const int tid = threadIdx.x;
    const int warp = tid >> 5;
    const int wm = warp >> 2;     // 0..1
    const int wn = warp & 3;      // 0..3
    const int rowbase = blockIdx.x * 64;

    wmma::fragment<wmma::accumulator, 16, 16, 16, float> acc[2][2];
#pragma unroll
    for (int i = 0; i < 2; i++)
#pragma unroll
        for (int j = 0; j < 2; j++) wmma::fill_fragment(acc[i][j], 0.0f);

    for (int k0 = 0; k0 < CH; k0 += 16) {
        // x tile: 64 rows x 16 k = 256 float4 (one per thread), split to hi/lo
        {
            int r = tid >> 2;
            int c4 = (tid & 3) * 4;
            int row = rowbase + r;
            float4 v = make_float4(0.f, 0.f, 0.f, 0.f);
            if (row < N)
                v = *reinterpret_cast<const float4*>(x + (size_t)row * CH + k0 + c4);
            float vv[4] = {v.x, v.y, v.z, v.w};
#pragma unroll
            for (int q = 0; q < 4; q++) {
                __nv_bfloat16 h = __float2bfloat16_rn(vv[q]);
                xhi[r * 16 + c4 + q] = h;
                xlo[r * 16 + c4 + q] = __float2bfloat16_rn(vv[q] - __bfloat162float(h));
            }
        }
        // W tile: 128 out x 16 k = 512 float4 (two per thread), split to hi/lo
#pragma unroll
        for (int t = 0; t < 2; t++) {
            int j = tid + t * 256;
            int o = j >> 2;
            int c4 = (j & 3) * 4;
            float4 v = *reinterpret_cast<const float4*>(W + (size_t)o * CH + k0 + c4);
            float vv[4] = {v.x, v.y, v.z, v.w};
#pragma unroll
            for (int q = 0; q < 4; q++) {
                __nv_bfloat16 h = __float2bfloat16_rn(vv[q]);
                whi[o * 16 + c4 + q] = h;
                wlo[o * 16 + c4 + q] = __float2bfloat16_rn(vv[q] - __bfloat162float(h));
            }
        }
        __syncthreads();

        wmma::fragment<wmma::matrix_a, 16, 16, 16, __nv_bfloat16, wmma::row_major> ahi[2], alo[2];
        wmma::fragment<wmma::matrix_b, 16, 16, 16, __nv_bfloat16, wmma::col_major> bhi[2], blo[2];
#pragma unroll
        for (int i = 0; i < 2; i++) {
            wmma::load_matrix_sync(ahi[i], &xhi[(wm * 32 + i * 16) * 16], 16);
            wmma::load_matrix_sync(alo[i], &xlo[(wm * 32 + i * 16) * 16], 16);
        }
#pragma unroll
        for (int j = 0; j < 2; j++) {
            wmma::load_matrix_sync(bhi[j], &whi[(wn * 32 + j * 16) * 16], 16);
            wmma::load_matrix_sync(blo[j], &wlo[(wn * 32 + j * 16) * 16], 16);
        }
#pragma unroll
        for (int i = 0; i < 2; i++)
#pragma unroll
            for (int j = 0; j < 2; j++) {
                wmma::mma_sync(acc[i][j], ahi[i], bhi[j], acc[i][j]);
                wmma::mma_sync(acc[i][j], ahi[i], blo[j], acc[i][j]);
                wmma::mma_sync(acc[i][j], alo[i], bhi[j], acc[i][j]);
            }
        __syncthreads();
    }

    // store (g_xw padded to 50048 rows: last block writes land in padding)
#pragma unroll
    for (int i = 0; i < 2; i++)
#pragma unroll
        for (int j = 0; j < 2; j++) {
            int row0 = rowbase + wm * 32 + i * 16;
            int col0 = wn * 32 + j * 16;
            wmma::store_matrix_sync(&g_xw[(size_t)row0 * CH + col0], acc[i][j],
                                    CH, wmma::mem_row_major);
        }
}

// ---------------- K5: per-node gather (1 warp/node) + fused BN stats ----------------
__global__ __launch_bounds__(256) void k_gather(float* __restrict__ out, int N) {
    __shared__ float s_sum[CH];
    __shared__ float s_sq[CH];
    const int t = threadIdx.x;
    if (t < CH) { s_sum[t] = 0.f; s_sq[t] = 0.f; }
    __syncthreads();

    const int node = (blockIdx.x * 256 + t) >> 5;
    const int lane = t & 31;

    if (node < N) {
        int j = g_off[node];
        const int end = g_off[node + 1];
        float dc = g_dis[node];

        // self loop: xw[node] * dc^2
        float4 acc = *reinterpret_cast<const float4*>(g_xw + (size_t)node * CH + lane * 4);
        float sl = dc * dc;
        acc.x *= sl; acc.y *= sl; acc.z *= sl; acc.w *= sl;

        for (; j + 4 <= end; j += 4) {
            int s0 = g_csrc[j], s1 = g_csrc[j + 1], s2 = g_csrc[j + 2], s3 = g_csrc[j + 3];
            float n0 = g_dis[s0] * dc, n1 = g_dis[s1] * dc;
            float n2 = g_dis[s2] * dc, n3 = g_dis[s3] * dc;
            float4 v0 = *reinterpret_cast<const float4*>(g_xw + (size_t)s0 * CH + lane * 4);
            float4 v1 = *reinterpret_cast<const float4*>(g_xw + (size_t)s1 * CH + lane * 4);
            float4 v2 = *reinterpret_cast<const float4*>(g_xw + (size_t)s2 * CH + lane * 4);
            float4 v3 = *reinterpret_cast<const float4*>(g_xw + (size_t)s3 * CH + lane * 4);
            acc.x = fmaf(n0, v0.x, acc.x); acc.y = fmaf(n0, v0.y, acc.y);
            acc.z = fmaf(n0, v0.z, acc.z); acc.w = fmaf(n0, v0.w, acc.w);
            acc.x = fmaf(n1, v1.x, acc.x); acc.y = fmaf(n1, v1.y, acc.y);
            acc.z = fmaf(n1, v1.z, acc.z); acc.w = fmaf(n1, v1.w, acc.w);
            acc.x = fmaf(n2, v2.x, acc.x); acc.y = fmaf(n2, v2.y, acc.y);
            acc.z = fmaf(n2, v2.z, acc.z); acc.w = fmaf(n2, v2.w, acc.w);
            acc.x = fmaf(n3, v3.x, acc.x); acc.y = fmaf(n3, v3.y, acc.y);
            acc.z = fmaf(n3, v3.z, acc.z); acc.w = fmaf(n3, v3.w, acc.w);
        }
        for (; j < end; j++) {
            int s = g_csrc[j];
            float nn = g_dis[s] * dc;
            float4 v = *reinterpret_cast<const float4*>(g_xw + (size_t)s * CH + lane * 4);
            acc.x = fmaf(nn, v.x, acc.x); acc.y = fmaf(nn, v.y, acc.y);
            acc.z = fmaf(nn, v.z, acc.z); acc.w = fmaf(nn, v.w, acc.w);
        }

        *reinterpret_cast<float4*>(out + (size_t)node * CH + lane * 4) = acc;

        int c4 = lane * 4;
        atomicAdd(&s_sum[c4 + 0], acc.x);
        atomicAdd(&s_sum[c4 + 1], acc.y);
        atomicAdd(&s_sum[c4 + 2], acc.z);
        atomicAdd(&s_sum[c4 + 3], acc.w);
        atomicAdd(&s_sq[c4 + 0], acc.x * acc.x);
        atomicAdd(&s_sq[c4 + 1], acc.y * acc.y);
        atomicAdd(&s_sq[c4 + 2], acc.z * acc.z);
        atomicAdd(&s_sq[c4 + 3], acc.w * acc.w);
    }
    __syncthreads();
    if (t < CH) {
        atomicAdd(&g_sum[t], s_sum[t]);
        atomicAdd(&g_sumsq[t], s_sq[t]);
    }
}

// ---------------- K6: finalize BN scale/shift ----------------
__global__ void k_bn_final(const float* __restrict__ gamma,
                           const float* __restrict__ beta, int N) {
    int c = threadIdx.x;
    float invN = 1.0f / (float)N;
    float mean = g_sum[c] * invN;
    float var = g_sumsq[c] * invN - mean * mean;
    float sc = gamma[c] * rsqrtf(var + BN_EPS);
    g_scale[c] = sc;
    g_shift[c] = beta[c] - mean * sc;   // GCN bias cancels under BN
}

// ---------------- K7: apply BN + ReLU ----------------
__global__ void k_apply(float* __restrict__ out, int total4) {
    int i = blockIdx.x * blockDim.x + threadIdx.x;
    if (i >= total4) return;
    float4 v = reinterpret_cast<float4*>(out)[i];
    int c = (i * 4) & (CH - 1);
    v.x = fmaxf(fmaf(v.x, g_scale[c + 0], g_shift[c + 0]), 0.f);
    v.y = fmaxf(fmaf(v.y, g_scale[c + 1], g_shift[c + 1]), 0.f);
    v.z = fmaxf(fmaf(v.z, g_scale[c + 2], g_shift[c + 2]), 0.f);
    v.w = fmaxf(fmaf(v.w, g_scale[c + 3], g_shift[c + 3]), 0.f);
    reinterpret_cast<float4*>(out)[i] = v;
}

// ---------------- launch ----------------
extern "C" void kernel_launch(void* const* d_in, const int* in_sizes, int n_in,
                              void* d_out, int out_size) {
    const float* x = (const float*)d_in[0];
    const int* ei = (const int*)d_in[1];
    const float* W = (const float*)d_in[2];
    // d_in[3] = bias: cancels under BatchNorm
    const float* gamma = (const float*)d_in[4];
    const float* beta = (const float*)d_in[5];
    float* out = (float*)d_out;

    int N = in_sizes[0] / CH;
    int E = in_sizes[1] / 2;

    static cudaStream_t s2 = nullptr;
    static cudaEvent_t evFork = nullptr, evJoin = nullptr;
    static void* p_cnt = nullptr;
    if (s2 == nullptr) {
        cudaStreamCreateWithFlags(&s2, cudaStreamNonBlocking);
        cudaEventCreateWithFlags(&evFork, cudaEventDisableTiming);
        cudaEventCreateWithFlags(&evJoin, cudaEventDisableTiming);
        cudaGetSymbolAddress(&p_cnt, g_cnt);
    }

    // fork: CSR build chain on s2, GEMM on main stream
    cudaEventRecord(evFork, 0);
    cudaStreamWaitEvent(s2, evFork, 0);

    cudaMemsetAsync(p_cnt, 0, (size_t)N * sizeof(int), s2);
    int eThreads4 = (E + 3) / 4;
    k_hist<<<(eThreads4 + 255) / 256, 256, 0, s2>>>(ei, E);
    k_scan<<<1, 1024, 0, s2>>>(N, E);
    k_fill<<<(eThreads4 + 255) / 256, 256, 0, s2>>>(ei, E);

    k_gemm<<<(N + 63) / 64, 256>>>(x, W, N);

    // join
    cudaEventRecord(evJoin, s2);
    cudaStreamWaitEvent(0, evJoin, 0);

    k_gather<<<(N * 32 + 255) / 256, 256>>>(out, N);
    k_bn_final<<<1, CH>>>(gamma, beta, N);
    int total4 = N * CH / 4;
    k_apply<<<(total4 + 255) / 256, 256>>>(out, total4);
}

// round 7
// speedup vs baseline: 1.4101x; 1.0584x over previous
#include <cuda_runtime.h>
#include <cuda_bf16.h>
#include <mma.h>

using namespace nvcuda;

// ---------------- problem constants ----------------
#define MAX_NODES 50000
#define PAD_NODES 50048         // 782 * 64, GEMM stores unguarded into padding
#define MAX_EDGES 810000
#define CH 128
#define BN_EPS 1e-5f
#define LDP 136                 // smem row pitch (bf16 elems): 272B -> conflict-free ldmatrix

// ---------------- scratch (device globals) ----------------
__device__ int   g_cnt[MAX_NODES];
__device__ int   g_off[MAX_NODES + 1];
__device__ int   g_rank[MAX_EDGES];
__device__ int   g_csrc[MAX_EDGES];
__device__ float g_dis[MAX_NODES];
__device__ float g_xw[(size_t)PAD_NODES * CH];
__device__ __nv_bfloat16 g_whi[CH * CH];
__device__ __nv_bfloat16 g_wlo[CH * CH];
__device__ float g_sum[CH];
__device__ float g_sumsq[CH];
__device__ float g_scale[CH];
__device__ float g_shift[CH];

// ---------------- K1: in-degree histogram + per-edge rank (4 edges/thread) ----------------
__global__ void k_hist(const int* __restrict__ ei, int E) {
    int base = (blockIdx.x * blockDim.x + threadIdx.x) * 4;
    if (base + 4 <= E) {
        int4 c = *reinterpret_cast<const int4*>(ei + (size_t)E + base);
        g_rank[base + 0] = atomicAdd(&g_cnt[c.x], 1);
        g_rank[base + 1] = atomicAdd(&g_cnt[c.y], 1);
        g_rank[base + 2] = atomicAdd(&g_cnt[c.z], 1);
        g_rank[base + 3] = atomicAdd(&g_cnt[c.w], 1);
    } else {
        for (int e = base; e < E; e++)
            g_rank[e] = atomicAdd(&g_cnt[ei[(size_t)E + e]], 1);
    }
}

// ---------------- K2: single-block exclusive scan + dis (+ zero BN accum) ----------------
__global__ __launch_bounds__(1024) void k_scan(int N, int E) {
    __shared__ int warp_sums[32];
    __shared__ int s_carry;
    const int lane = threadIdx.x & 31;
    const int wid = threadIdx.x >> 5;
    if (threadIdx.x < CH) { g_sum[threadIdx.x] = 0.f; g_sumsq[threadIdx.x] = 0.f; }
    if (threadIdx.x == 0) s_carry = 0;
    __syncthreads();

    for (int base = 0; base < N; base += 1024) {
        int i = base + threadIdx.x;
        int v = (i < N) ? g_cnt[i] : 0;
        int x = v;
#pragma unroll
        for (int d = 1; d < 32; d <<= 1) {
            int t = __shfl_up_sync(0xffffffffu, x, d);
            if (lane >= d) x += t;
        }
        if (lane == 31) warp_sums[wid] = x;
        __syncthreads();
        if (wid == 0) {
            int y = warp_sums[lane];
#pragma unroll
            for (int d = 1; d < 32; d <<= 1) {
                int t = __shfl_up_sync(0xffffffffu, y, d);
                if (lane >= d) y += t;
            }
            warp_sums[lane] = y;
        }
        __syncthreads();
        int incl = x + (wid > 0 ? warp_sums[wid - 1] : 0) + s_carry;
        int excl = incl - v;
        if (i < N) {
            g_off[i] = excl;
            g_dis[i] = rsqrtf((float)(v + 1));   // +1 self loop
        }
        __syncthreads();
        if (threadIdx.x == 1023) s_carry = incl;
        __syncthreads();
    }
    if (threadIdx.x == 0) g_off[N] = E;
}

// ---------------- K3: CSR fill, no atomics (4 edges/thread) ----------------
__global__ void k_fill(const int* __restrict__ ei, int E) {
    int base = (blockIdx.x * blockDim.x + threadIdx.x) * 4;
    if (base + 4 <= E) {
        int4 r = *reinterpret_cast<const int4*>(ei + base);
        int4 c = *reinterpret_cast<const int4*>(ei + (size_t)E + base);
        int4 k = *reinterpret_cast<const int4*>(g_rank + base);
        g_csrc[g_off[c.x] + k.x] = r.x;
        g_csrc[g_off[c.y] + k.y] = r.y;
        g_csrc[g_off[c.z] + k.z] = r.z;
        g_csrc[g_off[c.w] + k.w] = r.w;
    } else {
        for (int e = base; e < E; e++)
            g_csrc[g_off[ei[(size_t)E + e]] + g_rank[e]] = ei[e];
    }
}

// ---------------- K4a: pre-split W into bf16 hi/lo ----------------
__global__ void k_wsplit(const float* __restrict__ W) {
    int i = blockIdx.x * blockDim.x + threadIdx.x;   // 16384 elems
    float v = W[i];
    __nv_bfloat16 h = __float2bfloat16_rn(v);
    g_whi[i] = h;
    g_wlo[i] = __float2bfloat16_rn(v - __bfloat162float(h));
}

// ---------------- K4b: xw = x @ W^T via bf16-split wmma, whole-K resident ----------------
// 256 threads, tile 64(M) x 128(N), warps 2x4, warp tile 32x32 (2x2 frags).
// One __syncthreads, then 8 k-steps of uninterrupted mma.
__global__ __launch_bounds__(256) void k_gemm(const float* __restrict__ x, int N) {
    extern __shared__ __nv_bfloat16 sm[];
    __nv_bfloat16* xhi = sm;                    // 64  x LDP
    __nv_bfloat16* xlo = xhi + 64 * LDP;        // 64  x LDP
    __nv_bfloat16* whi = xlo + 64 * LDP;        // 128 x LDP
    __nv_bfloat16* wlo = whi + 128 * LDP;       // 128 x LDP

    const int tid = threadIdx.x;
    const int warp = tid >> 5;
    const int wm = warp >> 2;     // 0..1
    const int wn = warp & 3;      // 0..3
    const int rowbase = blockIdx.x * 64;

    // ---- load x tile (64 x 128 fp32 = 2048 float4), split hi/lo ----
#pragma unroll
    for (int it = 0; it < 8; it++) {
        int idx = tid + it * 256;
        int r = idx >> 5;
        int c4 = (idx & 31) * 4;
        int row = rowbase + r;
        float4 v = make_float4(0.f, 0.f, 0.f, 0.f);
        if (row < N)
            v = *reinterpret_cast<const float4*>(x + (size_t)row * CH + c4);
        float vv[4] = {v.x, v.y, v.z, v.w};
#pragma unroll
        for (int q = 0; q < 4; q++) {
            __nv_bfloat16 h = __float2bfloat16_rn(vv[q]);
            xhi[r * LDP + c4 + q] = h;
            xlo[r * LDP + c4 + q] = __float2bfloat16_rn(vv[q] - __bfloat162float(h));
        }
    }
    // ---- load pre-split W (128 x 128 bf16 x2 = 2048 uint4 each) ----
#pragma unroll
    for (int it = 0; it < 8; it++) {
        int idx = tid + it * 256;
        int o = idx >> 4;               // 128 rows, 16 chunks of 8 elems
        int c8 = (idx & 15) * 8;
        *reinterpret_cast<uint4*>(&whi[o * LDP + c8]) =
            *reinterpret_cast<const uint4*>(&g_whi[o * CH + c8]);
        *reinterpret_cast<uint4*>(&wlo[o * LDP + c8]) =
            *reinterpret_cast<const uint4*>(&g_wlo[o * CH + c8]);
    }
    __syncthreads();

    wmma::fragment<wmma::accumulator, 16, 16, 16, float> acc[2][2];
#pragma unroll
    for (int i = 0; i < 2; i++)
#pragma unroll
        for (int j = 0; j < 2; j++) wmma::fill_fragment(acc[i][j], 0.0f);

#pragma unroll
    for (int k = 0; k < 8; k++) {
        wmma::fragment<wmma::matrix_a, 16, 16, 16, __nv_bfloat16, wmma::row_major> ahi[2], alo[2];
        wmma::fragment<wmma::matrix_b, 16, 16, 16, __nv_bfloat16, wmma::col_major> bhi[2], blo[2];
#pragma unroll
        for (int i = 0; i < 2; i++) {
            wmma::load_matrix_sync(ahi[i], &xhi[(wm * 32 + i * 16) * LDP + k * 16], LDP);
            wmma::load_matrix_sync(alo[i], &xlo[(wm * 32 + i * 16) * LDP + k * 16], LDP);
        }
#pragma unroll
        for (int j = 0; j < 2; j++) {
            wmma::load_matrix_sync(bhi[j], &whi[(wn * 32 + j * 16) * LDP + k * 16], LDP);
            wmma::load_matrix_sync(blo[j], &wlo[(wn * 32 + j * 16) * LDP + k * 16], LDP);
        }
#pragma unroll
        for (int i = 0; i < 2; i++)
#pragma unroll
            for (int j = 0; j < 2; j++) {
                wmma::mma_sync(acc[i][j], ahi[i], bhi[j], acc[i][j]);
                wmma::mma_sync(acc[i][j], ahi[i], blo[j], acc[i][j]);
                wmma::mma_sync(acc[i][j], alo[i], bhi[j], acc[i][j]);
            }
    }

    // store (g_xw padded: last block rows land in padding)
#pragma unroll
    for (int i = 0; i < 2; i++)
#pragma unroll
        for (int j = 0; j < 2; j++) {
            int row0 = rowbase + wm * 32 + i * 16;
            int col0 = wn * 32 + j * 16;
            wmma::store_matrix_sync(&g_xw[(size_t)row0 * CH + col0], acc[i][j],
                                    CH, wmma::mem_row_major);
        }
}

// ---------------- K5: per-node gather (1 warp/node) + fused BN stats ----------------
__global__ __launch_bounds__(256) void k_gather(float* __restrict__ out, int N) {
    __shared__ float s_sum[CH];
    __shared__ float s_sq[CH];
    const int t = threadIdx.x;
    if (t < CH) { s_sum[t] = 0.f; s_sq[t] = 0.f; }
    __syncthreads();

    const int node = (blockIdx.x * 256 + t) >> 5;
    const int lane = t & 31;

    if (node < N) {
        int j = g_off[node];
        const int end = g_off[node + 1];
        float dc = g_dis[node];

        float4 acc = *reinterpret_cast<const float4*>(g_xw + (size_t)node * CH + lane * 4);
        float sl = dc * dc;
        acc.x *= sl; acc.y *= sl; acc.z *= sl; acc.w *= sl;

        for (; j + 4 <= end; j += 4) {
            int s0 = g_csrc[j], s1 = g_csrc[j + 1], s2 = g_csrc[j + 2], s3 = g_csrc[j + 3];
            float n0 = g_dis[s0] * dc, n1 = g_dis[s1] * dc;
            float n2 = g_dis[s2] * dc, n3 = g_dis[s3] * dc;
            float4 v0 = *reinterpret_cast<const float4*>(g_xw + (size_t)s0 * CH + lane * 4);
            float4 v1 = *reinterpret_cast<const float4*>(g_xw + (size_t)s1 * CH + lane * 4);
            float4 v2 = *reinterpret_cast<const float4*>(g_xw + (size_t)s2 * CH + lane * 4);
            float4 v3 = *reinterpret_cast<const float4*>(g_xw + (size_t)s3 * CH + lane * 4);
            acc.x = fmaf(n0, v0.x, acc.x); acc.y = fmaf(n0, v0.y, acc.y);
            acc.z = fmaf(n0, v0.z, acc.z); acc.w = fmaf(n0, v0.w, acc.w);
            acc.x = fmaf(n1, v1.x, acc.x); acc.y = fmaf(n1, v1.y, acc.y);
            acc.z = fmaf(n1, v1.z, acc.z); acc.w = fmaf(n1, v1.w, acc.w);
            acc.x = fmaf(n2, v2.x, acc.x); acc.y = fmaf(n2, v2.y, acc.y);
            acc.z = fmaf(n2, v2.z, acc.z); acc.w = fmaf(n2, v2.w, acc.w);
            acc.x = fmaf(n3, v3.x, acc.x); acc.y = fmaf(n3, v3.y, acc.y);
            acc.z = fmaf(n3, v3.z, acc.z); acc.w = fmaf(n3, v3.w, acc.w);
        }
        for (; j < end; j++) {
            int s = g_csrc[j];
            float nn = g_dis[s] * dc;
            float4 v = *reinterpret_cast<const float4*>(g_xw + (size_t)s * CH + lane * 4);
            acc.x = fmaf(nn, v.x, acc.x); acc.y = fmaf(nn, v.y, acc.y);
            acc.z = fmaf(nn, v.z, acc.z); acc.w = fmaf(nn, v.w, acc.w);
        }

        *reinterpret_cast<float4*>(out + (size_t)node * CH + lane * 4) = acc;

        int c4 = lane * 4;
        atomicAdd(&s_sum[c4 + 0], acc.x);
        atomicAdd(&s_sum[c4 + 1], acc.y);
        atomicAdd(&s_sum[c4 + 2], acc.z);
        atomicAdd(&s_sum[c4 + 3], acc.w);
        atomicAdd(&s_sq[c4 + 0], acc.x * acc.x);
        atomicAdd(&s_sq[c4 + 1], acc.y * acc.y);
        atomicAdd(&s_sq[c4 + 2], acc.z * acc.z);
        atomicAdd(&s_sq[c4 + 3], acc.w * acc.w);
    }
    __syncthreads();
    if (t < CH) {
        atomicAdd(&g_sum[t], s_sum[t]);
        atomicAdd(&g_sumsq[t], s_sq[t]);
    }
}

// ---------------- K6: finalize BN scale/shift ----------------
__global__ void k_bn_final(const float* __restrict__ gamma,
                           const float* __restrict__ beta, int N) {
    int c = threadIdx.x;
    float invN = 1.0f / (float)N;
    float mean = g_sum[c] * invN;
    float var = g_sumsq[c] * invN - mean * mean;
    float sc = gamma[c] * rsqrtf(var + BN_EPS);
    g_scale[c] = sc;
    g_shift[c] = beta[c] - mean * sc;   // GCN bias cancels under BN
}

// ---------------- K7: apply BN + ReLU ----------------
__global__ void k_apply(float* __restrict__ out, int total4) {
    int i = blockIdx.x * blockDim.x + threadIdx.x;
    if (i >= total4) return;
    float4 v = reinterpret_cast<float4*>(out)[i];
    int c = (i * 4) & (CH - 1);
    v.x = fmaxf(fmaf(v.x, g_scale[c + 0], g_shift[c + 0]), 0.f);
    v.y = fmaxf(fmaf(v.y, g_scale[c + 1], g_shift[c + 1]), 0.f);
    v.z = fmaxf(fmaf(v.z, g_scale[c + 2], g_shift[c + 2]), 0.f);
    v.w = fmaxf(fmaf(v.w, g_scale[c + 3], g_shift[c + 3]), 0.f);
    reinterpret_cast<float4*>(out)[i] = v;
}

// ---------------- launch ----------------
extern "C" void kernel_launch(void* const* d_in, const int* in_sizes, int n_in,
                              void* d_out, int out_size) {
    const float* x = (const float*)d_in[0];
    const int* ei = (const int*)d_in[1];
    const float* W = (const float*)d_in[2];
    // d_in[3] = bias: cancels under BatchNorm
    const float* gamma = (const float*)d_in[4];
    const float* beta = (const float*)d_in[5];
    float* out = (float*)d_out;

    int N = in_sizes[0] / CH;
    int E = in_sizes[1] / 2;

    const int GEMM_SMEM = (2 * 64 * LDP + 2 * 128 * LDP) * (int)sizeof(__nv_bfloat16);

    static cudaStream_t s2 = nullptr;
    static cudaEvent_t evFork = nullptr, evJoin = nullptr;
    static void* p_cnt = nullptr;
    if (s2 == nullptr) {
        cudaStreamCreateWithFlags(&s2, cudaStreamNonBlocking);
        cudaEventCreateWithFlags(&evFork, cudaEventDisableTiming);
        cudaEventCreateWithFlags(&evJoin, cudaEventDisableTiming);
        cudaGetSymbolAddress(&p_cnt, g_cnt);
        cudaFuncSetAttribute(k_gemm, cudaFuncAttributeMaxDynamicSharedMemorySize, GEMM_SMEM);
    }

    // fork: CSR build chain on s2, W-split + GEMM on main stream
    cudaEventRecord(evFork, 0);
    cudaStreamWaitEvent(s2, evFork, 0);

    cudaMemsetAsync(p_cnt, 0, (size_t)N * sizeof(int), s2);
    int eThreads4 = (E + 3) / 4;
    k_hist<<<(eThreads4 + 255) / 256, 256, 0, s2>>>(ei, E);
    k_scan<<<1, 1024, 0, s2>>>(N, E);
    k_fill<<<(eThreads4 + 255) / 256, 256, 0, s2>>>(ei, E);

    k_wsplit<<<CH * CH / 256, 256>>>(W);
    k_gemm<<<(N + 63) / 64, 256, GEMM_SMEM>>>(x, N);

    // join
    cudaEventRecord(evJoin, s2);
    cudaStreamWaitEvent(0, evJoin, 0);

    k_gather<<<(N * 32 + 255) / 256, 256>>>(out, N);
    k_bn_final<<<1, CH>>>(gamma, beta, N);
    int total4 = N * CH / 4;
    k_apply<<<(total4 + 255) / 256, 256>>>(out, total4);
}

// round 8
// speedup vs baseline: 1.6398x; 1.1628x over previous
#include <cuda_runtime.h>
#include <cuda_bf16.h>
#include <cuda_fp16.h>
#include <mma.h>

using namespace nvcuda;

// ---------------- problem constants ----------------
#define MAX_NODES 50000
#define PAD_NODES 50048         // 782 * 64, GEMM stores unguarded into padding
#define MAX_EDGES 810000
#define CH 128
#define BN_EPS 1e-5f
#define LDP 136                 // smem row pitch (bf16 elems)
#define LDF 136                 // epilogue fp32 smem pitch (mult of 8 for wmma store)

// ---------------- scratch (device globals) ----------------
__device__ int   g_cnt[MAX_NODES];
__device__ int   g_off[MAX_NODES + 1];
__device__ int   g_rank[MAX_EDGES];
__device__ int   g_csrc[MAX_EDGES];
__device__ float g_dis[MAX_NODES];
__device__ __half g_xwh[(size_t)PAD_NODES * CH];   // fp16 message matrix
__device__ __nv_bfloat16 g_whi[CH * CH];
__device__ __nv_bfloat16 g_wlo[CH * CH];
__device__ float g_sum[CH];
__device__ float g_sumsq[CH];

// ---------------- K1: in-degree histogram + per-edge rank (4 edges/thread) ----------------
__global__ void k_hist(const int* __restrict__ ei, int E) {
    int base = (blockIdx.x * blockDim.x + threadIdx.x) * 4;
    if (base + 4 <= E) {
        int4 c = *reinterpret_cast<const int4*>(ei + (size_t)E + base);
        g_rank[base + 0] = atomicAdd(&g_cnt[c.x], 1);
        g_rank[base + 1] = atomicAdd(&g_cnt[c.y], 1);
        g_rank[base + 2] = atomicAdd(&g_cnt[c.z], 1);
        g_rank[base + 3] = atomicAdd(&g_cnt[c.w], 1);
    } else {
        for (int e = base; e < E; e++)
            g_rank[e] = atomicAdd(&g_cnt[ei[(size_t)E + e]], 1);
    }
}

// ---------------- K2: single-block exclusive scan + dis (+ zero BN accum) ----------------
__global__ __launch_bounds__(1024) void k_scan(int N, int E) {
    __shared__ int warp_sums[32];
    __shared__ int s_carry;
    const int lane = threadIdx.x & 31;
    const int wid = threadIdx.x >> 5;
    if (threadIdx.x < CH) { g_sum[threadIdx.x] = 0.f; g_sumsq[threadIdx.x] = 0.f; }
    if (threadIdx.x == 0) s_carry = 0;
    __syncthreads();

    for (int base = 0; base < N; base += 1024) {
        int i = base + threadIdx.x;
        int v = (i < N) ? g_cnt[i] : 0;
        int x = v;
#pragma unroll
        for (int d = 1; d < 32; d <<= 1) {
            int t = __shfl_up_sync(0xffffffffu, x, d);
            if (lane >= d) x += t;
        }
        if (lane == 31) warp_sums[wid] = x;
        __syncthreads();
        if (wid == 0) {
            int y = warp_sums[lane];
#pragma unroll
            for (int d = 1; d < 32; d <<= 1) {
                int t = __shfl_up_sync(0xffffffffu, y, d);
                if (lane >= d) y += t;
            }
            warp_sums[lane] = y;
        }
        __syncthreads();
        int incl = x + (wid > 0 ? warp_sums[wid - 1] : 0) + s_carry;
        int excl = incl - v;
        if (i < N) {
            g_off[i] = excl;
            g_dis[i] = rsqrtf((float)(v + 1));   // +1 self loop
        }
        __syncthreads();
        if (threadIdx.x == 1023) s_carry = incl;
        __syncthreads();
    }
    if (threadIdx.x == 0) g_off[N] = E;
}

// ---------------- K3: CSR fill, no atomics (4 edges/thread) ----------------
__global__ void k_fill(const int* __restrict__ ei, int E) {
    int base = (blockIdx.x * blockDim.x + threadIdx.x) * 4;
    if (base + 4 <= E) {
        int4 r = *reinterpret_cast<const int4*>(ei + base);
        int4 c = *reinterpret_cast<const int4*>(ei + (size_t)E + base);
        int4 k = *reinterpret_cast<const int4*>(g_rank + base);
        g_csrc[g_off[c.x] + k.x] = r.x;
        g_csrc[g_off[c.y] + k.y] = r.y;
        g_csrc[g_off[c.z] + k.z] = r.z;
        g_csrc[g_off[c.w] + k.w] = r.w;
    } else {
        for (int e = base; e < E; e++)
            g_csrc[g_off[ei[(size_t)E + e]] + g_rank[e]] = ei[e];
    }
}

// ---------------- K4a: pre-split W into bf16 hi/lo ----------------
__global__ void k_wsplit(const float* __restrict__ W) {
    int i = blockIdx.x * blockDim.x + threadIdx.x;   // 16384 elems
    float v = W[i];
    __nv_bfloat16 h = __float2bfloat16_rn(v);
    g_whi[i] = h;
    g_wlo[i] = __float2bfloat16_rn(v - __bfloat162float(h));
}

// ---------------- K4b: xw = x @ W^T via bf16-split wmma, fp16 output ----------------
__global__ __launch_bounds__(256) void k_gemm(const float* __restrict__ x, int N) {
    extern __shared__ __nv_bfloat16 sm[];
    __nv_bfloat16* xhi = sm;                    // 64  x LDP
    __nv_bfloat16* xlo = xhi + 64 * LDP;        // 64  x LDP
    __nv_bfloat16* whi = xlo + 64 * LDP;        // 128 x LDP
    __nv_bfloat16* wlo = whi + 128 * LDP;       // 128 x LDP

    const int tid = threadIdx.x;
    const int warp = tid >> 5;
    const int wm = warp >> 2;     // 0..1
    const int wn = warp & 3;      // 0..3
    const int rowbase = blockIdx.x * 64;

    // ---- load x tile (64 x 128 fp32), split hi/lo ----
#pragma unroll
    for (int it = 0; it < 8; it++) {
        int idx = tid + it * 256;
        int r = idx >> 5;
        int c4 = (idx & 31) * 4;
        int row = rowbase + r;
        float4 v = make_float4(0.f, 0.f, 0.f, 0.f);
        if (row < N)
            v = *reinterpret_cast<const float4*>(x + (size_t)row * CH + c4);
        float vv[4] = {v.x, v.y, v.z, v.w};
#pragma unroll
        for (int q = 0; q < 4; q++) {
            __nv_bfloat16 h = __float2bfloat16_rn(vv[q]);
            xhi[r * LDP + c4 + q] = h;
            xlo[r * LDP + c4 + q] = __float2bfloat16_rn(vv[q] - __bfloat162float(h));
        }
    }
    // ---- load pre-split W ----
#pragma unroll
    for (int it = 0; it < 8; it++) {
        int idx = tid + it * 256;
        int o = idx >> 4;
        int c8 = (idx & 15) * 8;
        *reinterpret_cast<uint4*>(&whi[o * LDP + c8]) =
            *reinterpret_cast<const uint4*>(&g_whi[o * CH + c8]);
        *reinterpret_cast<uint4*>(&wlo[o * LDP + c8]) =
            *reinterpret_cast<const uint4*>(&g_wlo[o * CH + c8]);
    }
    __syncthreads();

    wmma::fragment<wmma::accumulator, 16, 16, 16, float> acc[2][2];
#pragma unroll
    for (int i = 0; i < 2; i++)
#pragma unroll
        for (int j = 0; j < 2; j++) wmma::fill_fragment(acc[i][j], 0.0f);

#pragma unroll
    for (int k = 0; k < 8; k++) {
        wmma::fragment<wmma::matrix_a, 16, 16, 16, __nv_bfloat16, wmma::row_major> ahi[2], alo[2];
        wmma::fragment<wmma::matrix_b, 16, 16, 16, __nv_bfloat16, wmma::col_major> bhi[2], blo[2];
#pragma unroll
        for (int i = 0; i < 2; i++) {
            wmma::load_matrix_sync(ahi[i], &xhi[(wm * 32 + i * 16) * LDP + k * 16], LDP);
            wmma::load_matrix_sync(alo[i], &xlo[(wm * 32 + i * 16) * LDP + k * 16], LDP);
        }
#pragma unroll
        for (int j = 0; j < 2; j++) {
            wmma::load_matrix_sync(bhi[j], &whi[(wn * 32 + j * 16) * LDP + k * 16], LDP);
            wmma::load_matrix_sync(blo[j], &wlo[(wn * 32 + j * 16) * LDP + k * 16], LDP);
        }
#pragma unroll
        for (int i = 0; i < 2; i++)
#pragma unroll
            for (int j = 0; j < 2; j++) {
                wmma::mma_sync(acc[i][j], ahi[i], bhi[j], acc[i][j]);
                wmma::mma_sync(acc[i][j], ahi[i], blo[j], acc[i][j]);
                wmma::mma_sync(acc[i][j], alo[i], bhi[j], acc[i][j]);
            }
    }

    // ---- epilogue: frags -> smem fp32 -> fp16 global ----
    __syncthreads();                               // all smem reads done
    float* sout = reinterpret_cast<float*>(sm);    // 64 x LDF fp32 (34.8KB, fits)
#pragma unroll
    for (int i = 0; i < 2; i++)
#pragma unroll
        for (int j = 0; j < 2; j++)
            wmma::store_matrix_sync(&sout[(size_t)(wm * 32 + i * 16) * LDF + wn * 32 + j * 16],
                                    acc[i][j], LDF, wmma::mem_row_major);
    __syncthreads();
#pragma unroll
    for (int it = 0; it < 4; it++) {
        int idx = tid + it * 256;                  // 1024 chunks of 8 elems
        int r = idx >> 4;
        int c8 = (idx & 15) * 8;
        const float* src = &sout[(size_t)r * LDF + c8];
        __half2 h[4];
#pragma unroll
        for (int q = 0; q < 4; q++)
            h[q] = __floats2half2_rn(src[q * 2], src[q * 2 + 1]);
        *reinterpret_cast<uint4*>(&g_xwh[(size_t)(rowbase + r) * CH + c8]) =
            *reinterpret_cast<uint4*>(h);
    }
}

// ---------------- K5: per-node gather (1 warp/node, fp16 rows) + fused BN stats ----------------
__global__ __launch_bounds__(256) void k_gather(float* __restrict__ out, int N) {
    __shared__ float s_sum[CH];
    __shared__ float s_sq[CH];
    const int t = threadIdx.x;
    if (t < CH) { s_sum[t] = 0.f; s_sq[t] = 0.f; }
    __syncthreads();

    const int node = (blockIdx.x * 256 + t) >> 5;
    const int lane = t & 31;

    if (node < N) {
        int j = g_off[node];
        const int end = g_off[node + 1];
        float dc = g_dis[node];

        // self loop: xwh[node] * dc^2
        float4 acc;
        {
            uint2 u = *reinterpret_cast<const uint2*>(g_xwh + (size_t)node * CH + lane * 4);
            float2 a = __half22float2(*reinterpret_cast<__half2*>(&u.x));
            float2 b = __half22float2(*reinterpret_cast<__half2*>(&u.y));
            float sl = dc * dc;
            acc = make_float4(a.x * sl, a.y * sl, b.x * sl, b.y * sl);
        }

        for (; j + 4 <= end; j += 4) {
            int s0 = g_csrc[j], s1 = g_csrc[j + 1], s2 = g_csrc[j + 2], s3 = g_csrc[j + 3];
            float n0 = g_dis[s0] * dc, n1 = g_dis[s1] * dc;
            float n2 = g_dis[s2] * dc, n3 = g_dis[s3] * dc;
            uint2 u0 = *reinterpret_cast<const uint2*>(g_xwh + (size_t)s0 * CH + lane * 4);
            uint2 u1 = *reinterpret_cast<const uint2*>(g_xwh + (size_t)s1 * CH + lane * 4);
            uint2 u2 = *reinterpret_cast<const uint2*>(g_xwh + (size_t)s2 * CH + lane * 4);
            uint2 u3 = *reinterpret_cast<const uint2*>(g_xwh + (size_t)s3 * CH + lane * 4);
            float2 a0 = __half22float2(*reinterpret_cast<__half2*>(&u0.x));
            float2 b0 = __half22float2(*reinterpret_cast<__half2*>(&u0.y));
            float2 a1 = __half22float2(*reinterpret_cast<__half2*>(&u1.x));
            float2 b1 = __half22float2(*reinterpret_cast<__half2*>(&u1.y));
            float2 a2 = __half22float2(*reinterpret_cast<__half2*>(&u2.x));
            float2 b2 = __half22float2(*reinterpret_cast<__half2*>(&u2.y));
            float2 a3 = __half22float2(*reinterpret_cast<__half2*>(&u3.x));
            float2 b3 = __half22float2(*reinterpret_cast<__half2*>(&u3.y));
            acc.x = fmaf(n0, a0.x, acc.x); acc.y = fmaf(n0, a0.y, acc.y);
            acc.z = fmaf(n0, b0.x, acc.z); acc.w = fmaf(n0, b0.y, acc.w);
            acc.x = fmaf(n1, a1.x, acc.x); acc.y = fmaf(n1, a1.y, acc.y);
            acc.z = fmaf(n1, b1.x, acc.z); acc.w = fmaf(n1, b1.y, acc.w);
            acc.x = fmaf(n2, a2.x, acc.x); acc.y = fmaf(n2, a2.y, acc.y);
            acc.z = fmaf(n2, b2.x, acc.z); acc.w = fmaf(n2, b2.y, acc.w);
            acc.x = fmaf(n3, a3.x, acc.x); acc.y = fmaf(n3, a3.y, acc.y);
            acc.z = fmaf(n3, b3.x, acc.z); acc.w = fmaf(n3, b3.y, acc.w);
        }
        for (; j < end; j++) {
            int s = g_csrc[j];
            float nn = g_dis[s] * dc;
            uint2 u = *reinterpret_cast<const uint2*>(g_xwh + (size_t)s * CH + lane * 4);
            float2 a = __half22float2(*reinterpret_cast<__half2*>(&u.x));
            float2 b = __half22float2(*reinterpret_cast<__half2*>(&u.y));
            acc.x = fmaf(nn, a.x, acc.x); acc.y = fmaf(nn, a.y, acc.y);
            acc.z = fmaf(nn, b.x, acc.z); acc.w = fmaf(nn, b.y, acc.w);
        }

        *reinterpret_cast<float4*>(out + (size_t)node * CH + lane * 4) = acc;

        int c4 = lane * 4;
        atomicAdd(&s_sum[c4 + 0], acc.x);
        atomicAdd(&s_sum[c4 + 1], acc.y);
        atomicAdd(&s_sum[c4 + 2], acc.z);
        atomicAdd(&s_sum[c4 + 3], acc.w);
        atomicAdd(&s_sq[c4 + 0], acc.x * acc.x);
        atomicAdd(&s_sq[c4 + 1], acc.y * acc.y);
        atomicAdd(&s_sq[c4 + 2], acc.z * acc.z);
        atomicAdd(&s_sq[c4 + 3], acc.w * acc.w);
    }
    __syncthreads();
    if (t < CH) {
        atomicAdd(&g_sum[t], s_sum[t]);
        atomicAdd(&g_sumsq[t], s_sq[t]);
    }
}

// ---------------- K6: apply BN + ReLU (scale/shift computed per block) ----------------
__global__ __launch_bounds__(256) void k_apply(const float* __restrict__ gamma,
                                               const float* __restrict__ beta,
                                               float* __restrict__ out, int N) {
    __shared__ float ssc[CH], ssh[CH];
    const int t = threadIdx.x;
    if (t < CH) {
        float invN = 1.0f / (float)N;
        float mean = g_sum[t] * invN;
        float var = g_sumsq[t] * invN - mean * mean;
        float sc = gamma[t] * rsqrtf(var + BN_EPS);
        ssc[t] = sc;
        ssh[t] = beta[t] - mean * sc;   // GCN bias cancels under BN
    }
    __syncthreads();

    int total4 = N * CH / 4;
    for (int i = blockIdx.x * blockDim.x + t; i < total4; i += gridDim.x * blockDim.x) {
        float4 v = reinterpret_cast<float4*>(out)[i];
        int c = (i * 4) & (CH - 1);
        v.x = fmaxf(fmaf(v.x, ssc[c + 0], ssh[c + 0]), 0.f);
        v.y = fmaxf(fmaf(v.y, ssc[c + 1], ssh[c + 1]), 0.f);
        v.z = fmaxf(fmaf(v.z, ssc[c + 2], ssh[c + 2]), 0.f);
        v.w = fmaxf(fmaf(v.w, ssc[c + 3], ssh[c + 3]), 0.f);
        reinterpret_cast<float4*>(out)[i] = v;
    }
}

// ---------------- launch ----------------
extern "C" void kernel_launch(void* const* d_in, const int* in_sizes, int n_in,
                              void* d_out, int out_size) {
    const float* x = (const float*)d_in[0];
    const int* ei = (const int*)d_in[1];
    const float* W = (const float*)d_in[2];
    // d_in[3] = bias: cancels under BatchNorm
    const float* gamma = (const float*)d_in[4];
    const float* beta = (const float*)d_in[5];
    float* out = (float*)d_out;

    int N = in_sizes[0] / CH;
    int E = in_sizes[1] / 2;

    const int GEMM_SMEM = (2 * 64 * LDP + 2 * 128 * LDP) * (int)sizeof(__nv_bfloat16);

    static cudaStream_t s2 = nullptr;
    static cudaEvent_t evFork = nullptr, evJoin = nullptr;
    static void* p_cnt = nullptr;
    if (s2 == nullptr) {
        cudaStreamCreateWithFlags(&s2, cudaStreamNonBlocking);
        cudaEventCreateWithFlags(&evFork, cudaEventDisableTiming);
        cudaEventCreateWithFlags(&evJoin, cudaEventDisableTiming);
        cudaGetSymbolAddress(&p_cnt, g_cnt);
        cudaFuncSetAttribute(k_gemm, cudaFuncAttributeMaxDynamicSharedMemorySize, GEMM_SMEM);
    }

    // fork: CSR build chain on s2, W-split + GEMM on main stream
    cudaEventRecord(evFork, 0);
    cudaStreamWaitEvent(s2, evFork, 0);

    cudaMemsetAsync(p_cnt, 0, (size_t)N * sizeof(int), s2);
    int eThreads4 = (E + 3) / 4;
    k_hist<<<(eThreads4 + 255) / 256, 256, 0, s2>>>(ei, E);
    k_scan<<<1, 1024, 0, s2>>>(N, E);
    k_fill<<<(eThreads4 + 255) / 256, 256, 0, s2>>>(ei, E);

    k_wsplit<<<CH * CH / 256, 256>>>(W);
    k_gemm<<<(N + 63) / 64, 256, GEMM_SMEM>>>(x, N);

    // join
    cudaEventRecord(evJoin, s2);
    cudaStreamWaitEvent(0, evJoin, 0);

    k_gather<<<(N * 32 + 255) / 256, 256>>>(out, N);
    k_apply<<<444, 256>>>(gamma, beta, out, N);
}